// round 4
// baseline (speedup 1.0000x reference)
#include <cuda_runtime.h>
#include <cuda_bf16.h>

#define NROWS    8192
#define NF       1024
#define NTHREADS 256
#define NBLOCKS  1024

__global__ __launch_bounds__(NTHREADS)
void kan_fused4(const float* __restrict__ x,
                const float* __restrict__ lnw,
                const float* __restrict__ lnb,
                const float* __restrict__ sw,
                const float* __restrict__ bw,
                const float* __restrict__ grid,
                float* __restrict__ out)
{
    // Swizzled transposed planes: coeff i of feature f lives at
    //   i*1024 + (f&3)*256 + (f>>2)
    // Thread tid owns features 4*tid+c  ->  tap addr = i*1024 + c*256 + tid,
    // bank = tid mod 32 = lane  ->  conflict-free under divergent plane index.
    __shared__ float s_swT[8 * NF];
    __shared__ float s_part[2][8];   // [{sum,sumsq}][warp]
    __shared__ float s_stat[2];      // {mu, rstd}

    const int tid  = threadIdx.x;
    const int wid  = tid >> 5;
    const int lane = tid & 31;

    // Stage spline weights pre-scaled by 1/6 into swizzled layout
    for (int f = tid; f < NF; f += NTHREADS) {
        float4 a = *reinterpret_cast<const float4*>(sw + f * 8);
        float4 b = *reinterpret_cast<const float4*>(sw + f * 8 + 4);
        const int base = ((f & 3) << 8) + (f >> 2);
        s_swT[0 * NF + base] = a.x * (1.0f/6.0f);
        s_swT[1 * NF + base] = a.y * (1.0f/6.0f);
        s_swT[2 * NF + base] = a.z * (1.0f/6.0f);
        s_swT[3 * NF + base] = a.w * (1.0f/6.0f);
        s_swT[4 * NF + base] = b.x * (1.0f/6.0f);
        s_swT[5 * NF + base] = b.y * (1.0f/6.0f);
        s_swT[6 * NF + base] = b.z * (1.0f/6.0f);
        s_swT[7 * NF + base] = b.w * (1.0f/6.0f);
    }

    const float g0    = grid[0];
    const float g11   = grid[11];
    const float inv_h = 11.0f / (g11 - g0);
    const float h     = (g11 - g0) * (1.0f / 11.0f);

    // Per-thread params for features 4*tid..4*tid+3 (vector loads)
    const float4 w4 = *reinterpret_cast<const float4*>(lnw + 4 * tid);
    const float4 b4 = *reinterpret_cast<const float4*>(lnb + 4 * tid);
    const float4 s4 = *reinterpret_cast<const float4*>(bw  + 4 * tid);
    float A[4], G[4], W[4];
    A[0] = w4.x * inv_h; A[1] = w4.y * inv_h; A[2] = w4.z * inv_h; A[3] = w4.w * inv_h;
    G[0] = (b4.x - g0) * inv_h; G[1] = (b4.y - g0) * inv_h;
    G[2] = (b4.z - g0) * inv_h; G[3] = (b4.w - g0) * inv_h;
    W[0] = s4.x; W[1] = s4.y; W[2] = s4.z; W[3] = s4.w;

    __syncthreads();

    for (int row = blockIdx.x; row < NROWS; row += NBLOCKS) {
        const float4 v4 = *reinterpret_cast<const float4*>(
                              x + (size_t)row * NF + 4 * tid);
        float v[4] = {v4.x, v4.y, v4.z, v4.w};

        float sum = (v[0] + v[1]) + (v[2] + v[3]);
        float sq  = fmaf(v[0], v[0], v[1] * v[1]) +
                    fmaf(v[2], v[2], v[3] * v[3]);

        #pragma unroll
        for (int off = 16; off; off >>= 1) {
            sum += __shfl_xor_sync(0xffffffffu, sum, off);
            sq  += __shfl_xor_sync(0xffffffffu, sq,  off);
        }
        if (lane == 0) { s_part[0][wid] = sum; s_part[1][wid] = sq; }
        __syncthreads();

        if (wid == 0) {
            float a = (lane < 8) ? s_part[0][lane] : 0.0f;
            float b = (lane < 8) ? s_part[1][lane] : 0.0f;
            #pragma unroll
            for (int off = 4; off; off >>= 1) {
                a += __shfl_xor_sync(0xffffffffu, a, off);
                b += __shfl_xor_sync(0xffffffffu, b, off);
            }
            if (lane == 0) {
                const float mu = a * (1.0f / NF);
                s_stat[0] = mu;
                s_stat[1] = rsqrtf(b * (1.0f / NF) - mu * mu + 1e-5f);
            }
        }
        __syncthreads();

        const float mu   = s_stat[0];
        const float rstd = s_stat[1];

        float4 res;
        float* resp = &res.x;

        #pragma unroll
        for (int c = 0; c < 4; c++) {
            const float xn = fmaf((v[c] - mu) * rstd, A[c], G[c]); // knot units
            const float n  = fmaf(xn, h, g0);                      // normed

            const float fj = floorf(xn);
            const int   j  = (int)fj;
            const float t  = xn - fj;
            const float u  = 1.0f - t;
            const float t2 = t * t;
            const float B0 = u * u * u;
            const float B1 = fmaf(fmaf(3.0f, t, -6.0f), t2, 4.0f);
            const float B3 = t2 * t;
            const float B2 = 6.0f - B0 - B1 - B3;

            const int i0 = j - 3;
            const float* wf = s_swT + (c << 8) + tid;   // bank = lane
            float s = 0.0f;
            if ((unsigned)(i0    ) < 8u) s = fmaf(B0, wf[(i0    ) << 10], s);
            if ((unsigned)(i0 + 1) < 8u) s = fmaf(B1, wf[(i0 + 1) << 10], s);
            if ((unsigned)(i0 + 2) < 8u) s = fmaf(B2, wf[(i0 + 2) << 10], s);
            if ((unsigned)(i0 + 3) < 8u) s = fmaf(B3, wf[(i0 + 3) << 10], s);

            const float sil = __fdividef(n, 1.0f + __expf(-n));
            resp[c] = fmaf(W[c], sil, s);
        }

        *reinterpret_cast<float4*>(out + (size_t)row * NF + 4 * tid) = res;
    }
}

extern "C" void kernel_launch(void* const* d_in, const int* in_sizes, int n_in,
                              void* d_out, int out_size)
{
    const float* x    = (const float*)d_in[0];
    const float* lnw  = (const float*)d_in[1];
    const float* lnb  = (const float*)d_in[2];
    const float* sw   = (const float*)d_in[3];
    const float* bw   = (const float*)d_in[4];
    const float* grid = (const float*)d_in[5];
    float* out = (float*)d_out;

    kan_fused4<<<NBLOCKS, NTHREADS>>>(x, lnw, lnb, sw, bw, grid, out);
}